// round 8
// baseline (speedup 1.0000x reference)
#include <cuda_runtime.h>
#include <cuda_fp16.h>
#include <stdint.h>

// SparseLinear: out[n,64] = segment_sum(value * W[col,:], rows) + bias
// Fixed-slot grouping, 8 column bins (col&7) so the fp32 W bin-slice (160KB)
// fits L1. SpMM pre-unpacks per lane; inner loop = 2 shfl + 1 addr + LDG.64
// + 2 FFMA per nnz. W read directly in fp32 (no convert pass).

#define OUTF    64
#define N_MAX   100032
#define NNZ_MAX 4000000
#define NB      8             // column bins (col & 7)
#define S       20            // slots per (row,bin); Binomial(T,1/8), T~Pois(40)
#define OVF_MAX 4096

__device__ int      g_counts[N_MAX * NB + 1];        // [+1] = overflow counter
__device__ unsigned g_slots[(size_t)N_MAX * NB * S]; // col<<16 | fp16(value)
__device__ int2     g_ovf[OVF_MAX];                  // {row, pack}

// ---------------- one-pass fill: count + place ----------------
__global__ void __launch_bounds__(256)
k_fill(const int* __restrict__ rows, const int* __restrict__ cols,
       const float* __restrict__ vals, int nnz, int n) {
    int* ovfcnt = &g_counts[n * NB];
    int base = blockIdx.x * 1024 + threadIdx.x;
    #pragma unroll
    for (int k = 0; k < 4; ++k) {
        int i = base + k * 256;                      // coalesced per iteration
        if (i < nnz) {
            int r = rows[i];
            int c = cols[i];
            unsigned pk = ((unsigned)c << 16)
                        | (unsigned)__half_as_ushort(__float2half_rn(vals[i]));
            int cidx = r * NB + (c & (NB - 1));
            int rank = atomicAdd(&g_counts[cidx], 1);
            if (rank < S) {
                __stcs(&g_slots[(size_t)cidx * S + rank], pk);
            } else {
                int o = atomicAdd(ovfcnt, 1);
                if (o < OVF_MAX) g_ovf[o] = make_int2(r, (int)pk);
            }
        }
    }
}

// ---------------- warp-per-row SpMM over 8 bins (+inline overflow fixup) ----------------
__global__ void __launch_bounds__(256)
k_spmm(const float* __restrict__ W, const float* __restrict__ bias,
       float* __restrict__ out, int n) {
    int row  = (blockIdx.x * blockDim.x + threadIdx.x) >> 5;
    int lane = threadIdx.x & 31;
    if (row >= n) return;

    float2 acc = ((const float2*)bias)[lane];        // lane owns cols [2l, 2l+1]
    const char* __restrict__ wlane = (const char*)W + (size_t)lane * 8;

    const int4* cp = (const int4*)&g_counts[row * NB];
    int4 c03 = cp[0], c47 = cp[1];
    int cnts[NB] = {c03.x, c03.y, c03.z, c03.w, c47.x, c47.y, c47.z, c47.w};

    #pragma unroll
    for (int bin = 0; bin < NB; ++bin) {
        int cnt = cnts[bin];
        if (cnt > S) cnt = S;
        size_t sb = ((size_t)row * NB + bin) * S;
        unsigned u = (lane < cnt) ? g_slots[sb + lane] : 0u;
        // pre-unpack this lane's nnz once (amortized over 32 lanes)
        int   boff = (int)(u >> 16) * 256;           // byte offset of W row (fp32)
        float vf   = __half2float(__ushort_as_half((unsigned short)(u & 0xFFFFu)));
        #pragma unroll 4
        for (int j = 0; j < cnt; ++j) {
            int   bo = __shfl_sync(0xFFFFFFFFu, boff, j);
            float v  = __shfl_sync(0xFFFFFFFFu, vf, j);
            float2 wf = *(const float2*)(wlane + bo);
            acc.x = fmaf(v, wf.x, acc.x);
            acc.y = fmaf(v, wf.y, acc.y);
        }
    }

    // inline overflow fixup: statistically ~tens of items chip-wide.
    int oc = g_counts[n * NB];
    if (oc > 0) {
        if (oc > OVF_MAX) oc = OVF_MAX;
        for (int i = 0; i < oc; ++i) {
            int2 it = g_ovf[i];
            if (it.x == row) {
                unsigned up = (unsigned)it.y;
                int   c = (int)(up >> 16);
                float v = __half2float(__ushort_as_half((unsigned short)(up & 0xFFFFu)));
                float2 wf = *(const float2*)(wlane + c * 256);
                acc.x = fmaf(v, wf.x, acc.x);
                acc.y = fmaf(v, wf.y, acc.y);
            }
        }
    }

    ((float2*)out)[(size_t)row * 32 + lane] = acc;
}

// ---------------- launch ----------------
extern "C" void kernel_launch(void* const* d_in, const int* in_sizes, int n_in,
                              void* d_out, int out_size) {
    const int*   index  = (const int*)d_in[0];    // [2, nnz]
    const float* value  = (const float*)d_in[1];  // [nnz]
    const float* weight = (const float*)d_in[3];  // [in_f, 64]
    const float* bias   = (const float*)d_in[4];  // [64]
    float* out = (float*)d_out;

    int nnz = in_sizes[1];
    int n   = out_size / OUTF;

    const int* rows = index;
    const int* cols = index + nnz;

    void* p = nullptr;
    cudaGetSymbolAddress(&p, g_counts);
    cudaMemsetAsync(p, 0, ((size_t)n * NB + 1) * sizeof(int));

    k_fill<<<(nnz + 1023) / 1024, 256>>>(rows, cols, value, nnz, n);

    int blocks = (n * 32 + 255) / 256;
    k_spmm<<<blocks, 256>>>(weight, bias, out, n);
}

// round 9
// speedup vs baseline: 1.2053x; 1.2053x over previous
#include <cuda_runtime.h>
#include <cuda_fp16.h>
#include <stdint.h>

// SparseLinear: out[n,64] = segment_sum(value * W[col,:], rows) + bias
// R7 pipeline (fixed-slot, 4 col bins, fp16 W, fused cvt+fill) with a
// half-warp-split SpMM: 2 nnz per iteration, lane owns 4 cols (float4 acc),
// pre-unpacked slots, butterfly merge at the end.

#define OUTF    64
#define N_MAX   100032
#define NNZ_MAX 4000000
#define INF_MAX 5120
#define NB      4             // column bins (col & 3)
#define S       32            // slots per (row,bin); mean 10
#define OVF_MAX 4096
#define CVTB    160           // blocks of k_fill dedicated to W convert

__device__ int      g_counts[N_MAX * NB + 1];          // [+1] = overflow counter
__device__ unsigned g_slots[(size_t)N_MAX * NB * S];   // col<<16 | fp16(value)
__device__ int2     g_ovf[OVF_MAX];                    // {row, pack}
__device__ __half   g_wh[INF_MAX * OUTF];              // fp16 W (row = 128B)

// ---------------- fill: cvt (first CVTB blocks) + count-and-place ----------------
__global__ void __launch_bounds__(256)
k_fill(const int* __restrict__ rows, const int* __restrict__ cols,
       const float* __restrict__ vals, int nnz,
       const float* __restrict__ W, int wtot, int n) {
    int b = blockIdx.x, t = threadIdx.x;
    if (b < CVTB) {    // convert W fp32 -> fp16, grid-stride
        for (int i = b * 256 + t; i < wtot; i += CVTB * 256)
            g_wh[i] = __float2half_rn(W[i]);
        return;
    }
    int* ovfcnt = &g_counts[n * NB];
    int base = (b - CVTB) * 1024 + t;
    #pragma unroll
    for (int k = 0; k < 4; ++k) {
        int i = base + k * 256;                        // coalesced per iteration
        if (i < nnz) {
            int r = rows[i];
            int c = cols[i];
            unsigned pk = ((unsigned)c << 16)
                        | (unsigned)__half_as_ushort(__float2half_rn(vals[i]));
            int cidx = (r << 2) | (c & (NB - 1));
            int rank = atomicAdd(&g_counts[cidx], 1);
            if (rank < S) {
                __stcs(&g_slots[((size_t)cidx << 5) + rank], pk);
            } else {
                int o = atomicAdd(ovfcnt, 1);
                if (o < OVF_MAX) g_ovf[o] = make_int2(r, (int)pk);
            }
        }
    }
}

// ---------------- half-warp-split SpMM (+inline overflow fixup) ----------------
__global__ void __launch_bounds__(256)
k_spmm(const float* __restrict__ bias, float* __restrict__ out, int n) {
    int row  = (blockIdx.x * blockDim.x + threadIdx.x) >> 5;
    int lane = threadIdx.x & 31;
    if (row >= n) return;
    int half = lane >> 4;          // 0: even nnz, 1: odd nnz
    int cgrp = lane & 15;          // owns cols [4*cgrp, 4*cgrp+3]

    const char* __restrict__ whb = (const char*)g_wh;
    float4 acc = make_float4(0.f, 0.f, 0.f, 0.f);

    int4 c4 = *(const int4*)&g_counts[row << 2];
    int cnts[NB] = {c4.x, c4.y, c4.z, c4.w};

    #pragma unroll
    for (int bin = 0; bin < NB; ++bin) {
        int cnt = cnts[bin];
        if (cnt > S) cnt = S;
        size_t sb = (size_t)((row << 2) | bin) << 5;
        unsigned u = (lane < cnt) ? g_slots[sb + lane] : 0u;
        int   bo = (int)(u >> 16) << 7;    // byte offset of fp16 W row (128B)
        float vf = __half2float(__ushort_as_half((unsigned short)(u & 0xFFFFu)));
        int src = half;
        #pragma unroll 2
        for (int j = 0; j < cnt; j += 2) {         // lanes ≥ cnt hold 0 → safe pad
            int   b2 = __shfl_sync(0xFFFFFFFFu, bo, src);
            float v  = __shfl_sync(0xFFFFFFFFu, vf, src);
            src += 2;
            uint2 wraw = *(const uint2*)(whb + b2 + cgrp * 8);   // 4 fp16 cols
            float2 w01 = __half22float2(*(const __half2*)&wraw.x);
            float2 w23 = __half22float2(*(const __half2*)&wraw.y);
            acc.x = fmaf(v, w01.x, acc.x);
            acc.y = fmaf(v, w01.y, acc.y);
            acc.z = fmaf(v, w23.x, acc.z);
            acc.w = fmaf(v, w23.y, acc.w);
        }
    }

    // merge even/odd halves (butterfly over lane bit 4)
    acc.x += __shfl_xor_sync(0xFFFFFFFFu, acc.x, 16);
    acc.y += __shfl_xor_sync(0xFFFFFFFFu, acc.y, 16);
    acc.z += __shfl_xor_sync(0xFFFFFFFFu, acc.z, 16);
    acc.w += __shfl_xor_sync(0xFFFFFFFFu, acc.w, 16);

    // inline overflow fixup: statistically 0 items; applied once (low half)
    int oc = g_counts[n << 2];
    if (oc > 0) {
        if (oc > OVF_MAX) oc = OVF_MAX;
        for (int i = 0; i < oc; ++i) {
            int2 it = g_ovf[i];
            if (it.x == row && half == 0) {
                unsigned up = (unsigned)it.y;
                float v = __half2float(__ushort_as_half((unsigned short)(up & 0xFFFFu)));
                uint2 wraw = *(const uint2*)(whb + ((int)(up >> 16) << 7) + cgrp * 8);
                float2 w01 = __half22float2(*(const __half2*)&wraw.x);
                float2 w23 = __half22float2(*(const __half2*)&wraw.y);
                acc.x = fmaf(v, w01.x, acc.x);
                acc.y = fmaf(v, w01.y, acc.y);
                acc.z = fmaf(v, w23.x, acc.z);
                acc.w = fmaf(v, w23.y, acc.w);
            }
        }
    }

    if (half == 0) {
        float4 bv = ((const float4*)bias)[cgrp];
        acc.x += bv.x; acc.y += bv.y; acc.z += bv.z; acc.w += bv.w;
        ((float4*)out)[(size_t)row * 16 + cgrp] = acc;   // 16 lanes x 16B = 256B
    }
}

// ---------------- launch ----------------
extern "C" void kernel_launch(void* const* d_in, const int* in_sizes, int n_in,
                              void* d_out, int out_size) {
    const int*   index  = (const int*)d_in[0];    // [2, nnz]
    const float* value  = (const float*)d_in[1];  // [nnz]
    const float* weight = (const float*)d_in[3];  // [in_f, 64]
    const float* bias   = (const float*)d_in[4];  // [64]
    float* out = (float*)d_out;

    int nnz  = in_sizes[1];
    int n    = out_size / OUTF;
    int wtot = in_sizes[3];

    const int* rows = index;
    const int* cols = index + nnz;

    void* p = nullptr;
    cudaGetSymbolAddress(&p, g_counts);
    cudaMemsetAsync(p, 0, ((size_t)n * NB + 1) * sizeof(int));

    int fb = CVTB + (nnz + 1023) / 1024;
    k_fill<<<fb, 256>>>(rows, cols, value, nnz, weight, wtot, n);

    int blocks = (n * 32 + 255) / 256;
    k_spmm<<<blocks, 256>>>(bias, out, n);
}

// round 10
// speedup vs baseline: 1.4321x; 1.1881x over previous
#include <cuda_runtime.h>
#include <cuda_fp16.h>
#include <stdint.h>

// SparseLinear: out[n,64] = segment_sum(value * W[col,:], rows) + bias
// Fixed-slot grouping (single 96-slot bin per row), fused cvt+fill, and a
// quarter-warp-split SpMM: 4 nnz/iteration, lane owns 8 cols (2x float4 acc),
// LDG.128 spans 4 fp16 W rows, butterfly merge (xor8, xor16) per row.

#define OUTF    64
#define N_MAX   100032
#define NNZ_MAX 4000000
#define INF_MAX 5120
#define S       96            // slots per row; Poisson(40), P(>=96) ~ 1e-12
#define OVF_MAX 4096
#define CVTB    160           // blocks of k_fill dedicated to W convert

__device__ int      g_counts[N_MAX + 1];           // [+1] = overflow counter
__device__ unsigned g_slots[(size_t)N_MAX * S];    // col<<16 | fp16(value)
__device__ int2     g_ovf[OVF_MAX];                // {row, pack}
__device__ __half   g_wh[INF_MAX * OUTF];          // fp16 W (row = 128B)

// ---------------- fill: cvt (first CVTB blocks) + count-and-place ----------------
__global__ void __launch_bounds__(256)
k_fill(const int* __restrict__ rows, const int* __restrict__ cols,
       const float* __restrict__ vals, int nnz,
       const float* __restrict__ W, int wtot, int n) {
    int b = blockIdx.x, t = threadIdx.x;
    if (b < CVTB) {    // convert W fp32 -> fp16, grid-stride
        for (int i = b * 256 + t; i < wtot; i += CVTB * 256)
            g_wh[i] = __float2half_rn(W[i]);
        return;
    }
    int* ovfcnt = &g_counts[n];
    int base = (b - CVTB) * 1024 + t;
    #pragma unroll
    for (int k = 0; k < 4; ++k) {
        int i = base + k * 256;                    // coalesced per iteration
        if (i < nnz) {
            int r = rows[i];
            unsigned pk = ((unsigned)cols[i] << 16)
                        | (unsigned)__half_as_ushort(__float2half_rn(vals[i]));
            int rank = atomicAdd(&g_counts[r], 1);
            if (rank < S) {
                __stcs(&g_slots[(size_t)r * S + rank], pk);
            } else {
                int o = atomicAdd(ovfcnt, 1);
                if (o < OVF_MAX) g_ovf[o] = make_int2(r, (int)pk);
            }
        }
    }
}

// ---------------- quarter-warp-split SpMM (+inline overflow fixup) ----------------
__global__ void __launch_bounds__(256)
k_spmm(const float* __restrict__ bias, float* __restrict__ out, int n) {
    int row  = (blockIdx.x * blockDim.x + threadIdx.x) >> 5;
    int lane = threadIdx.x & 31;
    if (row >= n) return;
    int q  = lane >> 3;            // quarter 0..3: processes nnz j+q
    int cg = lane & 7;             // owns cols [8*cg, 8*cg+7]

    const char* __restrict__ wq = (const char*)g_wh + cg * 16;   // 8 fp16 cols
    float4 a0 = make_float4(0.f, 0.f, 0.f, 0.f);
    float4 a1 = make_float4(0.f, 0.f, 0.f, 0.f);

    int cnt = g_counts[row];
    if (cnt > S) cnt = S;
    const unsigned* __restrict__ sl = &g_slots[(size_t)row * S];

    for (int base = 0; base < cnt; base += 32) {
        int k = base + lane;
        unsigned u = (k < cnt) ? sl[k] : 0u;       // 128B coalesced strip
        int   bo = (int)(u >> 16) << 7;            // fp16 W row byte offset
        float vf = __half2float(__ushort_as_half((unsigned short)(u & 0xFFFFu)));
        int m = cnt - base; if (m > 32) m = 32;
        int src = q;
        #pragma unroll 2
        for (int j = 0; j < m; j += 4) {           // padded lanes: v=0 -> safe
            int   b2 = __shfl_sync(0xFFFFFFFFu, bo, src);
            float v  = __shfl_sync(0xFFFFFFFFu, vf, src);
            src += 4;
            uint4 wr = *(const uint4*)(wq + b2);   // 16B = 8 fp16 cols
            float2 w01 = __half22float2(*(const __half2*)&wr.x);
            float2 w23 = __half22float2(*(const __half2*)&wr.y);
            float2 w45 = __half22float2(*(const __half2*)&wr.z);
            float2 w67 = __half22float2(*(const __half2*)&wr.w);
            a0.x = fmaf(v, w01.x, a0.x);  a0.y = fmaf(v, w01.y, a0.y);
            a0.z = fmaf(v, w23.x, a0.z);  a0.w = fmaf(v, w23.y, a0.w);
            a1.x = fmaf(v, w45.x, a1.x);  a1.y = fmaf(v, w45.y, a1.y);
            a1.z = fmaf(v, w67.x, a1.z);  a1.w = fmaf(v, w67.y, a1.w);
        }
    }

    // inline overflow fixup BEFORE merge (statistically empty); quarter 0 only
    int oc = g_counts[n];
    if (oc > 0) {
        if (oc > OVF_MAX) oc = OVF_MAX;
        for (int i = 0; i < oc; ++i) {
            int2 it = g_ovf[i];
            if (it.x == row && q == 0) {
                unsigned up = (unsigned)it.y;
                float v = __half2float(__ushort_as_half((unsigned short)(up & 0xFFFFu)));
                uint4 wr = *(const uint4*)(wq + ((int)(up >> 16) << 7));
                float2 w01 = __half22float2(*(const __half2*)&wr.x);
                float2 w23 = __half22float2(*(const __half2*)&wr.y);
                float2 w45 = __half22float2(*(const __half2*)&wr.z);
                float2 w67 = __half22float2(*(const __half2*)&wr.w);
                a0.x = fmaf(v, w01.x, a0.x);  a0.y = fmaf(v, w01.y, a0.y);
                a0.z = fmaf(v, w23.x, a0.z);  a0.w = fmaf(v, w23.y, a0.w);
                a1.x = fmaf(v, w45.x, a1.x);  a1.y = fmaf(v, w45.y, a1.y);
                a1.z = fmaf(v, w67.x, a1.z);  a1.w = fmaf(v, w67.y, a1.w);
            }
        }
    }

    // merge quarters: same cg across lane bits 3,4
    #pragma unroll
    for (int d = 8; d <= 16; d <<= 1) {
        a0.x += __shfl_xor_sync(0xFFFFFFFFu, a0.x, d);
        a0.y += __shfl_xor_sync(0xFFFFFFFFu, a0.y, d);
        a0.z += __shfl_xor_sync(0xFFFFFFFFu, a0.z, d);
        a0.w += __shfl_xor_sync(0xFFFFFFFFu, a0.w, d);
        a1.x += __shfl_xor_sync(0xFFFFFFFFu, a1.x, d);
        a1.y += __shfl_xor_sync(0xFFFFFFFFu, a1.y, d);
        a1.z += __shfl_xor_sync(0xFFFFFFFFu, a1.z, d);
        a1.w += __shfl_xor_sync(0xFFFFFFFFu, a1.w, d);
    }

    if (q == 0) {
        float4 b0 = ((const float4*)bias)[2 * cg];
        float4 b1 = ((const float4*)bias)[2 * cg + 1];
        a0.x += b0.x; a0.y += b0.y; a0.z += b0.z; a0.w += b0.w;
        a1.x += b1.x; a1.y += b1.y; a1.z += b1.z; a1.w += b1.w;
        float4* orow = (float4*)out + (size_t)row * 16;
        orow[2 * cg]     = a0;                     // 8 lanes x 32B = 256B row
        orow[2 * cg + 1] = a1;
    }
}

// ---------------- launch ----------------
extern "C" void kernel_launch(void* const* d_in, const int* in_sizes, int n_in,
                              void* d_out, int out_size) {
    const int*   index  = (const int*)d_in[0];    // [2, nnz]
    const float* value  = (const float*)d_in[1];  // [nnz]
    const float* weight = (const float*)d_in[3];  // [in_f, 64]
    const float* bias   = (const float*)d_in[4];  // [64]
    float* out = (float*)d_out;

    int nnz  = in_sizes[1];
    int n    = out_size / OUTF;
    int wtot = in_sizes[3];

    const int* rows = index;
    const int* cols = index + nnz;

    void* p = nullptr;
    cudaGetSymbolAddress(&p, g_counts);
    cudaMemsetAsync(p, 0, ((size_t)n + 1) * sizeof(int));

    int fb = CVTB + (nnz + 1023) / 1024;
    k_fill<<<fb, 256>>>(rows, cols, value, nnz, weight, wtot, n);

    int blocks = (n * 32 + 255) / 256;
    k_spmm<<<blocks, 256>>>(bias, out, n);
}

// round 11
// speedup vs baseline: 1.4789x; 1.0327x over previous
#include <cuda_runtime.h>
#include <cuda_fp16.h>
#include <stdint.h>

// SparseLinear: out[n,64] = segment_sum(value * W[col,:], rows) + bias
// Fixed-slot grouping (96 slots/row), fused cvt+fill; quarter-warp-split SpMM
// with HFMA2 (half2) accumulation in the inner loop, fp32 flush per 32-strip.

#define OUTF    64
#define N_MAX   100032
#define NNZ_MAX 4000000
#define INF_MAX 5120
#define S       96            // slots per row; Poisson(40), P(>=96) ~ 1e-12
#define OVF_MAX 4096
#define CVTB    160           // blocks of k_fill dedicated to W convert

__device__ int      g_counts[N_MAX + 1];           // [+1] = overflow counter
__device__ unsigned g_slots[(size_t)N_MAX * S];    // col<<16 | fp16(value); >=cnt stays 0
__device__ int2     g_ovf[OVF_MAX];                // {row, pack}
__device__ __half   g_wh[INF_MAX * OUTF];          // fp16 W (row = 128B)

// ---------------- fill: cvt (first CVTB blocks) + count-and-place ----------------
__global__ void __launch_bounds__(256)
k_fill(const int* __restrict__ rows, const int* __restrict__ cols,
       const float* __restrict__ vals, int nnz,
       const float* __restrict__ W, int wtot, int n) {
    int b = blockIdx.x, t = threadIdx.x;
    if (b < CVTB) {    // convert W fp32 -> fp16, grid-stride
        for (int i = b * 256 + t; i < wtot; i += CVTB * 256)
            g_wh[i] = __float2half_rn(W[i]);
        return;
    }
    int* ovfcnt = &g_counts[n];
    int base = (b - CVTB) * 1024 + t;
    #pragma unroll
    for (int k = 0; k < 4; ++k) {
        int i = base + k * 256;                    // coalesced per iteration
        if (i < nnz) {
            int r = rows[i];
            unsigned pk = ((unsigned)cols[i] << 16)
                        | (unsigned)__half_as_ushort(__float2half_rn(vals[i]));
            int rank = atomicAdd(&g_counts[r], 1);
            if (rank < S) {
                __stcs(&g_slots[(size_t)r * S + rank], pk);
            } else {
                int o = atomicAdd(ovfcnt, 1);
                if (o < OVF_MAX) g_ovf[o] = make_int2(r, (int)pk);
            }
        }
    }
}

// ---------------- quarter-warp SpMM, HFMA2 inner loop ----------------
__global__ void __launch_bounds__(256)
k_spmm(const float* __restrict__ bias, float* __restrict__ out, int n) {
    int row  = (blockIdx.x * blockDim.x + threadIdx.x) >> 5;
    int lane = threadIdx.x & 31;
    if (row >= n) return;
    int q  = lane >> 3;            // quarter 0..3: processes nnz j+q
    int cg = lane & 7;             // owns cols [8*cg, 8*cg+7]

    const char* __restrict__ wq = (const char*)g_wh + cg * 16;   // 8 fp16 cols
    float4 a0 = make_float4(0.f, 0.f, 0.f, 0.f);
    float4 a1 = make_float4(0.f, 0.f, 0.f, 0.f);

    int cnt = g_counts[row];
    if (cnt > S) cnt = S;
    const unsigned* __restrict__ sl = &g_slots[(size_t)row * S];

    for (int base = 0; base < cnt; base += 32) {
        unsigned u = sl[base + lane];              // strip <= S, pad lanes read 0
        int m = cnt - base; if (m > 32) m = 32;
        int src = q;
        __half2 h0 = __float2half2_rn(0.f), h1 = h0, h2 = h0, h3 = h0;
        #pragma unroll 2
        for (int j = 0; j < m; j += 4) {           // padded lanes: v=0 -> safe
            unsigned up = __shfl_sync(0xFFFFFFFFu, u, src);
            src += 4;
            int bo = (int)(up >> 16) << 7;         // fp16 W row byte offset
            __half2 vh = __half2half2(__ushort_as_half((unsigned short)(up & 0xFFFFu)));
            uint4 wr = *(const uint4*)(wq + bo);   // 16B = 8 fp16 cols
            h0 = __hfma2(vh, *(const __half2*)&wr.x, h0);
            h1 = __hfma2(vh, *(const __half2*)&wr.y, h1);
            h2 = __hfma2(vh, *(const __half2*)&wr.z, h2);
            h3 = __hfma2(vh, *(const __half2*)&wr.w, h3);
        }
        float2 f;                                  // flush strip to fp32
        f = __half22float2(h0); a0.x += f.x; a0.y += f.y;
        f = __half22float2(h1); a0.z += f.x; a0.w += f.y;
        f = __half22float2(h2); a1.x += f.x; a1.y += f.y;
        f = __half22float2(h3); a1.z += f.x; a1.w += f.y;
    }

    // inline overflow fixup BEFORE merge (statistically empty); quarter 0 only
    int oc = g_counts[n];
    if (oc > 0) {
        if (oc > OVF_MAX) oc = OVF_MAX;
        for (int i = 0; i < oc; ++i) {
            int2 it = g_ovf[i];
            if (it.x == row && q == 0) {
                unsigned up = (unsigned)it.y;
                float v = __half2float(__ushort_as_half((unsigned short)(up & 0xFFFFu)));
                uint4 wr = *(const uint4*)(wq + ((int)(up >> 16) << 7));
                float2 w01 = __half22float2(*(const __half2*)&wr.x);
                float2 w23 = __half22float2(*(const __half2*)&wr.y);
                float2 w45 = __half22float2(*(const __half2*)&wr.z);
                float2 w67 = __half22float2(*(const __half2*)&wr.w);
                a0.x = fmaf(v, w01.x, a0.x);  a0.y = fmaf(v, w01.y, a0.y);
                a0.z = fmaf(v, w23.x, a0.z);  a0.w = fmaf(v, w23.y, a0.w);
                a1.x = fmaf(v, w45.x, a1.x);  a1.y = fmaf(v, w45.y, a1.y);
                a1.z = fmaf(v, w67.x, a1.z);  a1.w = fmaf(v, w67.y, a1.w);
            }
        }
    }

    // merge quarters: same cg across lane bits 3,4
    #pragma unroll
    for (int d = 8; d <= 16; d <<= 1) {
        a0.x += __shfl_xor_sync(0xFFFFFFFFu, a0.x, d);
        a0.y += __shfl_xor_sync(0xFFFFFFFFu, a0.y, d);
        a0.z += __shfl_xor_sync(0xFFFFFFFFu, a0.z, d);
        a0.w += __shfl_xor_sync(0xFFFFFFFFu, a0.w, d);
        a1.x += __shfl_xor_sync(0xFFFFFFFFu, a1.x, d);
        a1.y += __shfl_xor_sync(0xFFFFFFFFu, a1.y, d);
        a1.z += __shfl_xor_sync(0xFFFFFFFFu, a1.z, d);
        a1.w += __shfl_xor_sync(0xFFFFFFFFu, a1.w, d);
    }

    if (q == 0) {
        float4 b0 = ((const float4*)bias)[2 * cg];
        float4 b1 = ((const float4*)bias)[2 * cg + 1];
        a0.x += b0.x; a0.y += b0.y; a0.z += b0.z; a0.w += b0.w;
        a1.x += b1.x; a1.y += b1.y; a1.z += b1.z; a1.w += b1.w;
        float4* orow = (float4*)out + (size_t)row * 16;
        orow[2 * cg]     = a0;                     // 8 lanes x 32B = 256B row
        orow[2 * cg + 1] = a1;
    }
}

// ---------------- launch ----------------
extern "C" void kernel_launch(void* const* d_in, const int* in_sizes, int n_in,
                              void* d_out, int out_size) {
    const int*   index  = (const int*)d_in[0];    // [2, nnz]
    const float* value  = (const float*)d_in[1];  // [nnz]
    const float* weight = (const float*)d_in[3];  // [in_f, 64]
    const float* bias   = (const float*)d_in[4];  // [64]
    float* out = (float*)d_out;

    int nnz  = in_sizes[1];
    int n    = out_size / OUTF;
    int wtot = in_sizes[3];

    const int* rows = index;
    const int* cols = index + nnz;

    void* p = nullptr;
    cudaGetSymbolAddress(&p, g_counts);
    cudaMemsetAsync(p, 0, ((size_t)n + 1) * sizeof(int));

    int fb = CVTB + (nnz + 1023) / 1024;
    k_fill<<<fb, 256>>>(rows, cols, value, nnz, weight, wtot, n);

    int blocks = (n * 32 + 255) / 256;
    k_spmm<<<blocks, 256>>>(bias, out, n);
}